// round 5
// baseline (speedup 1.0000x reference)
#include <cuda_runtime.h>

#define NB 512
#define C_IN 32
#define F1 64
#define F2 128
#define BN_EPS 1e-5f
#define PARTS 8
#define NBLK (NB * PARTS)   // 4096 streaming blocks
#define TB 64               // tail workers (last TB ticket holders, co-resident)

// ---- scratch (no allocations allowed; zero-initialized at load) ----
__device__ float g_part[PARTS * NB * C_IN];   // per-part channel sums
__device__ float g_meanT[C_IN * NB];          // segment means, [ch][row]
__device__ float g_hT[F1 * NB];               // fc1 activations, [col][row]
__device__ float g_s1[F1], g_o1[F1];          // BN1 affine
__device__ int      g_segcnt[NB];             // per-segment part counter
__device__ unsigned g_ticket;                 // global completion ticket
__device__ unsigned g_b1, g_b1b;              // tail barrier + cleanup counter

// ---------------------------------------------------------------------------
// ONE fused kernel. 4096 blocks x 256 threads.
//  - stream 1/8 segment slice -> partial channel sums
//  - 8th arriver per segment reduces partials -> g_meanT, resets seg counter
//  - every block takes a ticket; last TB become tail workers:
//      spin(ticket==NBLK) -> fc1 col + BN1 stats -> 64-way barrier ->
//      BN1+relu+fc2+BN2 (block-local, 2 out cols) -> out
// ---------------------------------------------------------------------------
__global__ void __launch_bounds__(256) k_fused(
    const float4* __restrict__ x,  const int*   __restrict__ len,
    const float* __restrict__ W1,  const float* __restrict__ b1,
    const float* __restrict__ g1,  const float* __restrict__ be1,
    const float* __restrict__ W2,  const float* __restrict__ b2,
    const float* __restrict__ g2,  const float* __restrict__ be2,
    float* __restrict__ out)
{
    __shared__ int    sl[256];
    __shared__ float4 red[256];
    __shared__ float  sred[2 * 256];
    __shared__ float  ss1[F1], so1[F1];
    __shared__ float  sbn2[4];
    __shared__ int    sbroad;

    const int bid = blockIdx.x;
    const int seg = bid >> 3;
    const int p   = bid & (PARTS - 1);
    const int tid = threadIdx.x;

    // --- segment offset: sum of len[i] for i < seg (block-redundant) ---
    {
        int v = 0;
        if (tid < seg)       v += len[tid];
        if (tid + 256 < seg) v += len[tid + 256];
        sl[tid] = v;
    }
    __syncthreads();
    #pragma unroll
    for (int st = 128; st > 0; st >>= 1) {
        if (tid < st) sl[tid] += sl[tid + st];
        __syncthreads();
    }
    const int off = sl[0];
    const int L   = len[seg];
    const int r0  = off + (L * p)       / PARTS;
    const int r1  = off + (L * (p + 1)) / PARTS;

    // --- stream rows [r0, r1): 4 independent float4 loads in flight ---
    {
        int js = r0 * 8 + tid;
        int je = r1 * 8;
        float4 a0 = make_float4(0.f,0.f,0.f,0.f);
        float4 a1 = a0, a2 = a0, a3 = a0;
        int j = js;
        for (; j + 768 < je; j += 1024) {
            float4 v0 = __ldcs(&x[j]);
            float4 v1 = __ldcs(&x[j + 256]);
            float4 v2 = __ldcs(&x[j + 512]);
            float4 v3 = __ldcs(&x[j + 768]);
            a0.x += v0.x; a0.y += v0.y; a0.z += v0.z; a0.w += v0.w;
            a1.x += v1.x; a1.y += v1.y; a1.z += v1.z; a1.w += v1.w;
            a2.x += v2.x; a2.y += v2.y; a2.z += v2.z; a2.w += v2.w;
            a3.x += v3.x; a3.y += v3.y; a3.z += v3.z; a3.w += v3.w;
        }
        for (; j < je; j += 256) {
            float4 v0 = __ldcs(&x[j]);
            a0.x += v0.x; a0.y += v0.y; a0.z += v0.z; a0.w += v0.w;
        }
        a0.x += a1.x + a2.x + a3.x;   // fixed order, deterministic
        a0.y += a1.y + a2.y + a3.y;
        a0.z += a1.z + a2.z + a3.z;
        a0.w += a1.w + a2.w + a3.w;

        red[tid] = a0;
    }
    __syncthreads();
    #pragma unroll
    for (int st = 128; st >= 8; st >>= 1) {
        if (tid < st) {
            float4 o = red[tid + st];
            red[tid].x += o.x; red[tid].y += o.y;
            red[tid].z += o.z; red[tid].w += o.w;
        }
        __syncthreads();
    }
    if (tid < 8)
        ((float4*)g_part)[(p * NB + seg) * 8 + tid] = red[tid];
    __syncthreads();

    // --- publish partial; 8th arriver reduces means for this segment ---
    if (tid == 0) {
        __threadfence();
        sbroad = atomicAdd(&g_segcnt[seg], 1);
    }
    __syncthreads();
    if (sbroad == PARTS - 1) {
        if (tid == 0) __threadfence();   // acquire other parts' writes
        __syncthreads();
        if (tid < C_IN) {
            float s = 0.f;
            #pragma unroll
            for (int q = 0; q < PARTS; q++)
                s += g_part[(q * NB + seg) * C_IN + tid];
            g_meanT[tid * NB + seg] = s / (float)L;
        }
        if (tid == 0) g_segcnt[seg] = 0;   // reset for next replay
        __syncthreads();
    }

    // --- global ticket; last TB blocks become tail workers ---
    if (tid == 0) {
        __threadfence();
        unsigned t = atomicAdd(&g_ticket, 1u) + 1u;
        sbroad = (t > (unsigned)(NBLK - TB)) ? (int)(t - (NBLK - TB) - 1) : -1;
    }
    __syncthreads();
    const int role = sbroad;
    if (role < 0) return;

    // wait for all blocks (=> all partials and all means published)
    if (tid == 0) {
        while (*((volatile unsigned*)&g_ticket) < (unsigned)NBLK) { }
        __threadfence();
    }
    __syncthreads();

    // ---- Phase A: fc1 column c = role, plus BN1 stats ----
    {
        const int c = role;
        float acc0 = __ldg(&b1[c]), acc1 = acc0;
        #pragma unroll
        for (int k = 0; k < C_IN; k++) {
            float w = __ldg(&W1[k * F1 + c]);               // block-uniform
            acc0 = fmaf(g_meanT[k * NB + tid],       w, acc0);   // coalesced
            acc1 = fmaf(g_meanT[k * NB + tid + 256], w, acc1);   // coalesced
        }
        g_hT[c * NB + tid]       = acc0;
        g_hT[c * NB + tid + 256] = acc1;

        sred[tid]       = acc0 + acc1;
        sred[256 + tid] = acc0 * acc0 + acc1 * acc1;
        __syncthreads();
        #pragma unroll
        for (int st = 128; st > 0; st >>= 1) {
            if (tid < st) {
                sred[tid]       += sred[tid + st];
                sred[256 + tid] += sred[256 + tid + st];
            }
            __syncthreads();
        }
        if (tid == 0) {
            float mu  = sred[0]   * (1.0f / (float)NB);
            float var = sred[256] * (1.0f / (float)NB) - mu * mu;
            float sc  = g1[c] * rsqrtf(var + BN_EPS);
            g_s1[c] = sc;
            g_o1[c] = be1[c] - mu * sc;
        }
    }

    // ---- 64-way spin barrier + counter cleanup ----
    __syncthreads();
    if (tid == 0) {
        __threadfence();
        atomicAdd(&g_b1, 1u);
        while (*((volatile unsigned*)&g_b1) < (unsigned)TB) { }
        __threadfence();
        unsigned o = atomicAdd(&g_b1b, 1u);
        if (o == TB - 1) {              // all workers passed both spins
            g_b1 = 0; g_b1b = 0; g_ticket = 0;
        }
    }
    __syncthreads();

    if (tid < F1) { ss1[tid] = g_s1[tid]; so1[tid] = g_o1[tid]; }
    __syncthreads();

    // ---- Phase B: out cols c0=2*role, c1=2*role+1 (block-local BN2) ----
    {
        const int c0 = 2 * role, c1 = 2 * role + 1;
        float a00 = __ldg(&b2[c0]), a01 = __ldg(&b2[c1]);
        float a10 = a00,            a11 = a01;
        #pragma unroll 8
        for (int k = 0; k < F1; k++) {
            float h0 = g_hT[k * NB + tid];
            float h1 = g_hT[k * NB + tid + 256];
            float sc = ss1[k], of = so1[k];
            float r0v = fmaxf(fmaf(h0, sc, of), 0.f);
            float r1v = fmaxf(fmaf(h1, sc, of), 0.f);
            float w0 = __ldg(&W2[k * F2 + c0]);   // block-uniform
            float w1 = __ldg(&W2[k * F2 + c1]);
            a00 = fmaf(r0v, w0, a00);
            a01 = fmaf(r0v, w1, a01);
            a10 = fmaf(r1v, w0, a10);
            a11 = fmaf(r1v, w1, a11);
        }

        // BN2 stats col c0 (deterministic tree)
        sred[tid]       = a00 + a10;
        sred[256 + tid] = a00 * a00 + a10 * a10;
        __syncthreads();
        #pragma unroll
        for (int st = 128; st > 0; st >>= 1) {
            if (tid < st) {
                sred[tid]       += sred[tid + st];
                sred[256 + tid] += sred[256 + tid + st];
            }
            __syncthreads();
        }
        if (tid == 0) {
            float mu  = sred[0]   * (1.0f / (float)NB);
            float var = sred[256] * (1.0f / (float)NB) - mu * mu;
            float sc  = g2[c0] * rsqrtf(var + BN_EPS);
            sbn2[0] = sc;
            sbn2[1] = be2[c0] - mu * sc;
        }
        __syncthreads();

        // BN2 stats col c1
        sred[tid]       = a01 + a11;
        sred[256 + tid] = a01 * a01 + a11 * a11;
        __syncthreads();
        #pragma unroll
        for (int st = 128; st > 0; st >>= 1) {
            if (tid < st) {
                sred[tid]       += sred[tid + st];
                sred[256 + tid] += sred[256 + tid + st];
            }
            __syncthreads();
        }
        if (tid == 0) {
            float mu  = sred[0]   * (1.0f / (float)NB);
            float var = sred[256] * (1.0f / (float)NB) - mu * mu;
            float sc  = g2[c1] * rsqrtf(var + BN_EPS);
            sbn2[2] = sc;
            sbn2[3] = be2[c1] - mu * sc;
        }
        __syncthreads();

        float s0 = sbn2[0], o0 = sbn2[1], s1 = sbn2[2], o1 = sbn2[3];
        out[tid * F2 + c0]         = fmaf(a00, s0, o0);
        out[tid * F2 + c1]         = fmaf(a01, s1, o1);
        out[(tid + 256) * F2 + c0] = fmaf(a10, s0, o0);
        out[(tid + 256) * F2 + c1] = fmaf(a11, s1, o1);
    }
}

// ---------------------------------------------------------------------------
extern "C" void kernel_launch(void* const* d_in, const int* in_sizes, int n_in,
                              void* d_out, int out_size) {
    const float* x     = (const float*)d_in[0];
    const int*   len   = (const int*)  d_in[1];
    const float* W1    = (const float*)d_in[2];
    const float* b1    = (const float*)d_in[3];
    const float* g1    = (const float*)d_in[4];
    const float* beta1 = (const float*)d_in[5];
    const float* W2    = (const float*)d_in[6];
    const float* b2    = (const float*)d_in[7];
    const float* g2    = (const float*)d_in[8];
    const float* beta2 = (const float*)d_in[9];
    float* out = (float*)d_out;

    k_fused<<<NBLK, 256>>>((const float4*)x, len,
                           W1, b1, g1, beta1, W2, b2, g2, beta2, out);
}